// round 3
// baseline (speedup 1.0000x reference)
#include <cuda_runtime.h>

#define EDGES  1600000
#define NODES  50000
#define NGRAPH 16
#define KSLOT  8
#define HID    32

// ---------------- static scratch ----------------
__device__ int   g_is64;
__device__ int   g_src[EDGES];
__device__ int   g_dst[EDGES];
__device__ int2  g_sed[EDGES];          // sorted-by-dst: {src, dist(bits)}
__device__ int   g_cnt[NODES];
__device__ int   g_off[NODES + 1];
__device__ int   g_cur[NODES];
__device__ int   g_batch[NODES];
__device__ float g_XB[NODES * HID];     // x[n] @ W1[4:8]
__device__ float g_H[NODES * HID];
__device__ float g_S[NODES * KSLOT];
__device__ float g_POOL[NGRAPH * KSLOT * HID];
__device__ float g_Z[NGRAPH * KSLOT * 4];

__device__ __forceinline__ float siluf(float a) {
    return __fdividef(a, 1.0f + __expf(-a));
}

// ---------------- zero + dtype detect ----------------
__global__ void k_zero(const unsigned int* __restrict__ ei) {
    int i = blockIdx.x * 256 + threadIdx.x;
    if (i < NODES) g_cnt[i] = 0;
    if (i < NGRAPH * KSLOT * HID) g_POOL[i] = 0.0f;
    if (blockIdx.x == 0 && threadIdx.x == 0) {
        int is64 = 1;
        for (int k = 1; k < 64; k += 2)
            if (ei[k] != 0u) { is64 = 0; break; }
        g_is64 = is64;
    }
}

// ---------------- convert indices + dst histogram ----------------
__global__ void k_prep(const void* __restrict__ ei, const void* __restrict__ batch) {
    int i = blockIdx.x * 256 + threadIdx.x;      // grid covers EDGES exactly
    int is64 = g_is64;
    int s, d;
    if (is64) {
        const long long* q = (const long long*)ei;
        s = (int)q[i];
        d = (int)q[EDGES + i];
    } else {
        const int* q = (const int*)ei;
        s = q[i];
        d = q[EDGES + i];
    }
    g_src[i] = s;
    g_dst[i] = d;
    atomicAdd(&g_cnt[d], 1);
    if (i < NODES) {
        g_batch[i] = is64 ? (int)((const long long*)batch)[i]
                          : ((const int*)batch)[i];
    }
}

// ---------------- exclusive scan of degree histogram (1 block) ----------------
__global__ void k_scan() {
    __shared__ int sums[1024];
    const int CH = (NODES + 1023) / 1024;        // 49
    int t = threadIdx.x;
    int base = t * CH;
    int local = 0;
    for (int i = 0; i < CH; i++) {
        int n = base + i;
        if (n < NODES) local += g_cnt[n];
    }
    sums[t] = local;
    __syncthreads();
    for (int ofs = 1; ofs < 1024; ofs <<= 1) {
        int v = (t >= ofs) ? sums[t - ofs] : 0;
        __syncthreads();
        sums[t] += v;
        __syncthreads();
    }
    int run = sums[t] - local;                   // exclusive prefix
    for (int i = 0; i < CH; i++) {
        int n = base + i;
        if (n < NODES) {
            g_off[n] = run;
            g_cur[n] = run;
            run += g_cnt[n];
        }
    }
    if (t == 1023) g_off[NODES] = run;           // == EDGES
}

// ---------------- scatter edges into CSR buckets + precompute dist ----------------
__global__ void k_scatter(const float* __restrict__ pos) {
    int e = blockIdx.x * 256 + threadIdx.x;
    int d = g_dst[e];
    int s = g_src[e];
    float dx = __ldg(pos + 3 * s + 0) - __ldg(pos + 3 * d + 0);
    float dy = __ldg(pos + 3 * s + 1) - __ldg(pos + 3 * d + 1);
    float dz = __ldg(pos + 3 * s + 2) - __ldg(pos + 3 * d + 2);
    float dist = sqrtf(dx * dx + dy * dy + dz * dz);
    int p = atomicAdd(&g_cur[d], 1);
    g_sed[p] = make_int2(s, __float_as_int(dist));
}

// ---------------- XB[n,j] = sum_i x[n,i] * w1[4+i, j] ----------------
__global__ void k_xb(const float* __restrict__ x, const float* __restrict__ w1) {
    int i = blockIdx.x * 256 + threadIdx.x;      // NODES*HID == EDGES grid
    int n = i >> 5, j = i & 31;
    float4 xv = __ldg((const float4*)(x + ((size_t)n << 2)));
    float a = xv.x * __ldg(w1 + 4 * 32 + j);
    a = fmaf(xv.y, __ldg(w1 + 5 * 32 + j), a);
    a = fmaf(xv.z, __ldg(w1 + 6 * 32 + j), a);
    a = fmaf(xv.w, __ldg(w1 + 7 * 32 + j), a);
    g_XB[i] = a;
}

// ---------------- main: per-node gather, silu-mean, W2, softmax ----------------
__global__ void __launch_bounds__(256) k_main(const float* __restrict__ x,
                                              const float* __restrict__ w1,
                                              const float* __restrict__ b1,
                                              const float* __restrict__ w2,
                                              const float* __restrict__ b2,
                                              const float* __restrict__ pw,
                                              const float* __restrict__ pb) {
    __shared__ float spw[HID * KSLOT];
    __shared__ float spb[KSLOT];
    __shared__ float sh[8][HID];
    int t = threadIdx.x;
    for (int i = t; i < HID * KSLOT; i += 256) spw[i] = pw[i];
    if (t < KSLOT) spb[t] = pb[t];
    __syncthreads();

    int lane = t & 31;
    int w = t >> 5;

    float w1a0 = __ldg(w1 + 0 * 32 + lane);
    float w1a1 = __ldg(w1 + 1 * 32 + lane);
    float w1a2 = __ldg(w1 + 2 * 32 + lane);
    float w1a3 = __ldg(w1 + 3 * 32 + lane);
    float cw   = __ldg(w1 + 8 * 32 + lane);
    float b1r  = __ldg(b1 + lane);
    float b2r  = __ldg(b2 + lane);
    float w2c[32];
#pragma unroll
    for (int j = 0; j < 32; j++) w2c[j] = __ldg(w2 + j * 32 + lane);

    int gw = (blockIdx.x << 3) + w;
    int nwarp = gridDim.x << 3;

    for (int node = gw; node < NODES; node += nwarp) {
        int beg = g_off[node];
        int end = g_off[node + 1];
        float4 xd = __ldg((const float4*)(x + ((size_t)node << 2)));
        float base = b1r;
        base = fmaf(xd.x, w1a0, base);
        base = fmaf(xd.y, w1a1, base);
        base = fmaf(xd.z, w1a2, base);
        base = fmaf(xd.w, w1a3, base);

        float acc0 = 0.0f, acc1 = 0.0f;
        int i = beg;
        for (; i + 2 <= end; i += 2) {
            int2 e0 = __ldg(g_sed + i);
            int2 e1 = __ldg(g_sed + i + 1);
            float xb0 = __ldg(g_XB + (((size_t)e0.x) << 5) + lane);
            float xb1 = __ldg(g_XB + (((size_t)e1.x) << 5) + lane);
            float p0 = fmaf(__int_as_float(e0.y), cw, base) + xb0;
            float p1 = fmaf(__int_as_float(e1.y), cw, base) + xb1;
            acc0 += siluf(p0);
            acc1 += siluf(p1);
        }
        if (i < end) {
            int2 e0 = __ldg(g_sed + i);
            float xb0 = __ldg(g_XB + (((size_t)e0.x) << 5) + lane);
            acc0 += siluf(fmaf(__int_as_float(e0.y), cw, base) + xb0);
        }

        int deg = end - beg;
        float inv = (deg > 0) ? __fdividef(1.0f, (float)deg) : 0.0f;
        float hsil = (acc0 + acc1) * inv;

        sh[w][lane] = hsil;
        __syncwarp();
        float h = (deg > 0) ? b2r : 0.0f;
#pragma unroll
        for (int j = 0; j < 32; j++) h = fmaf(sh[w][j], w2c[j], h);
        __syncwarp();

        g_H[((size_t)node << 5) + lane] = h;
        sh[w][lane] = h;
        __syncwarp();

        if (lane < 8) {
            float l = spb[lane];
#pragma unroll
            for (int j = 0; j < 32; j++) l = fmaf(sh[w][j], spw[j * 8 + lane], l);
            float m = l;
            m = fmaxf(m, __shfl_xor_sync(0xff, m, 4, 8));
            m = fmaxf(m, __shfl_xor_sync(0xff, m, 2, 8));
            m = fmaxf(m, __shfl_xor_sync(0xff, m, 1, 8));
            float ex = __expf(l - m);
            float sum = ex;
            sum += __shfl_xor_sync(0xff, sum, 4, 8);
            sum += __shfl_xor_sync(0xff, sum, 2, 8);
            sum += __shfl_xor_sync(0xff, sum, 1, 8);
            g_S[((size_t)node << 3) + lane] = __fdividef(ex, sum);
        }
        __syncwarp();
    }
}

// ---------------- pooling ----------------
__global__ void __launch_bounds__(256) k_pool() {
    int b = blockIdx.x & 15;
    int slice = blockIdx.x >> 4;

    int lo = 0, hi = NODES;
    while (lo < hi) { int m = (lo + hi) >> 1; if (g_batch[m] < b) lo = m + 1; else hi = m; }
    int start = lo;
    lo = start; hi = NODES;
    while (lo < hi) { int m = (lo + hi) >> 1; if (g_batch[m] < b + 1) lo = m + 1; else hi = m; }
    int end = lo;

    int cnt = end - start;
    int s0 = start + (cnt * slice) / 4;
    int s1 = start + (cnt * (slice + 1)) / 4;

    int k = threadIdx.x >> 5;
    int j = threadIdx.x & 31;

    float acc = 0.0f;
#pragma unroll 4
    for (int n = s0; n < s1; n++)
        acc = fmaf(__ldg(g_S + (size_t)n * KSLOT + k), __ldg(g_H + (size_t)n * HID + j), acc);

    atomicAdd(&g_POOL[(b * KSLOT + k) * HID + j], acc);
}

// ---------------- z = pooled @ toz_w + toz_b ----------------
__global__ void k_z(const float* __restrict__ tw, const float* __restrict__ tb) {
    int t = threadIdx.x;               // 512 threads
    int b = t >> 5;
    int k = (t >> 2) & 7;
    int d = t & 3;
    float acc = tb[d];
#pragma unroll
    for (int j = 0; j < HID; j++)
        acc = fmaf(g_POOL[b * 256 + k * 32 + j], tw[j * 4 + d], acc);
    g_Z[t] = acc;
}

// ---------------- decode ----------------
__global__ void __launch_bounds__(128) k_dec(const float* __restrict__ w1,
                                             const float* __restrict__ b1,
                                             const float* __restrict__ w2,
                                             const float* __restrict__ b2,
                                             float* __restrict__ out) {
    __shared__ __align__(16) float sz[NGRAPH * KSLOT * 4];
    __shared__ __align__(16) float sw1[128];
    __shared__ float sb1[32];
    __shared__ __align__(16) float sw2[128];
    __shared__ float sb2v[4];

    int t = threadIdx.x;
    for (int i = t; i < 512; i += 128) sz[i] = g_Z[i];
    sw1[t] = w1[(t & 3) * 32 + (t >> 2)];
    sw2[t] = w2[t];
    if (t < 32) sb1[t] = b1[t];
    if (t < 4)  sb2v[t] = b2[t];
    __syncthreads();

    int n = blockIdx.x * 128 + t;
    if (n >= NODES) return;

    float4 sa = *(const float4*)(g_S + (size_t)n * KSLOT);
    float4 sbv = *(const float4*)(g_S + (size_t)n * KSLOT + 4);
    float s[8] = { sa.x, sa.y, sa.z, sa.w, sbv.x, sbv.y, sbv.z, sbv.w };

#pragma unroll 1
    for (int b = 0; b < NGRAPH; b++) {
        float q0 = 0.f, q1 = 0.f, q2 = 0.f, q3 = 0.f;
#pragma unroll
        for (int k = 0; k < 8; k++) {
            float4 zv = *(const float4*)&sz[(b * 8 + k) * 4];
            q0 = fmaf(s[k], zv.x, q0);
            q1 = fmaf(s[k], zv.y, q1);
            q2 = fmaf(s[k], zv.z, q2);
            q3 = fmaf(s[k], zv.w, q3);
        }
        float o0 = sb2v[0], o1 = sb2v[1], o2 = sb2v[2], o3 = sb2v[3];
#pragma unroll
        for (int j = 0; j < 32; j++) {
            float4 wc = *(const float4*)&sw1[j * 4];
            float tt = sb1[j];
            tt = fmaf(q0, wc.x, tt);
            tt = fmaf(q1, wc.y, tt);
            tt = fmaf(q2, wc.z, tt);
            tt = fmaf(q3, wc.w, tt);
            tt = siluf(tt);
            float4 wr = *(const float4*)&sw2[j * 4];
            o0 = fmaf(tt, wr.x, o0);
            o1 = fmaf(tt, wr.y, o1);
            o2 = fmaf(tt, wr.z, o2);
            o3 = fmaf(tt, wr.w, o3);
        }
        *(float4*)(out + ((size_t)b * NODES + n) * 4) = make_float4(o0, o1, o2, o3);
    }
}

// ---------------- launch ----------------
extern "C" void kernel_launch(void* const* d_in, const int* in_sizes, int n_in,
                              void* d_out, int out_size) {
    const float* x      = (const float*)d_in[0];
    const float* pos    = (const float*)d_in[1];
    const void*  ei     = d_in[2];
    const void*  batch  = d_in[3];
    const float* enc_w1 = (const float*)d_in[4];
    const float* enc_b1 = (const float*)d_in[5];
    const float* enc_w2 = (const float*)d_in[6];
    const float* enc_b2 = (const float*)d_in[7];
    const float* pool_w = (const float*)d_in[8];
    const float* pool_b = (const float*)d_in[9];
    const float* toz_w  = (const float*)d_in[10];
    const float* toz_b  = (const float*)d_in[11];
    const float* dec_w1 = (const float*)d_in[12];
    const float* dec_b1 = (const float*)d_in[13];
    const float* dec_w2 = (const float*)d_in[14];
    const float* dec_b2 = (const float*)d_in[15];
    float* out = (float*)d_out;

    k_zero<<<(NODES + 255) / 256, 256>>>((const unsigned int*)ei);
    k_prep<<<EDGES / 256, 256>>>(ei, batch);
    k_scan<<<1, 1024>>>();
    k_scatter<<<EDGES / 256, 256>>>(pos);
    k_xb<<<EDGES / 256, 256>>>(x, enc_w1);
    k_main<<<1184, 256>>>(x, enc_w1, enc_b1, enc_w2, enc_b2, pool_w, pool_b);
    k_pool<<<64, 256>>>();
    k_z<<<1, 512>>>(toz_w, toz_b);
    k_dec<<<(NODES + 127) / 128, 128>>>(dec_w1, dec_b1, dec_w2, dec_b2, out);
}

// round 4
// speedup vs baseline: 1.3059x; 1.3059x over previous
#include <cuda_runtime.h>

#define EDGES  1600000
#define NODES  50000
#define NGRAPH 16
#define KSLOT  8
#define HID    32
#define SCANB  ((NODES + 1023) / 1024)   // 49

// ---------------- static scratch ----------------
__device__ int   g_is64;
__device__ int   g_src[EDGES];
__device__ int   g_dst[EDGES];
__device__ int4  g_sed4[EDGES / 2];      // sorted-by-dst: pairs of {src, dist_bits}
__device__ int   g_cnt[NODES];
__device__ int   g_ps[NODES];            // per-block inclusive scan
__device__ int   g_part[64];
__device__ int   g_poff[64];
__device__ int   g_off[NODES + 1];
__device__ int   g_cur[NODES];
__device__ int   g_batch[NODES];
__device__ float g_XB[NODES * HID];      // x[n] @ W1[4:8]
__device__ float g_H[NODES * HID];
__device__ float g_S[NODES * KSLOT];
__device__ float g_POOL[NGRAPH * KSLOT * HID];
__device__ float g_Z[NGRAPH * KSLOT * 4];

__device__ __forceinline__ float siluf(float a) {
    return __fdividef(a, 1.0f + __expf(-a));
}

// ---------------- zero + dtype detect ----------------
__global__ void k_zero(const unsigned int* __restrict__ ei) {
    int i = blockIdx.x * 256 + threadIdx.x;
    if (i < NODES) g_cnt[i] = 0;
    if (i < NGRAPH * KSLOT * HID) g_POOL[i] = 0.0f;
    if (blockIdx.x == 0 && threadIdx.x == 0) {
        int is64 = 1;
        for (int k = 1; k < 64; k += 2)
            if (ei[k] != 0u) { is64 = 0; break; }
        g_is64 = is64;
    }
}

// ---------------- convert indices + dst histogram ----------------
__global__ void k_prep(const void* __restrict__ ei, const void* __restrict__ batch) {
    int i = blockIdx.x * 256 + threadIdx.x;      // grid covers EDGES exactly
    int is64 = g_is64;
    int s, d;
    if (is64) {
        const long long* q = (const long long*)ei;
        s = (int)q[i];
        d = (int)q[EDGES + i];
    } else {
        const int* q = (const int*)ei;
        s = q[i];
        d = q[EDGES + i];
    }
    g_src[i] = s;
    g_dst[i] = d;
    atomicAdd(&g_cnt[d], 1);
    if (i < NODES) {
        g_batch[i] = is64 ? (int)((const long long*)batch)[i]
                          : ((const int*)batch)[i];
    }
}

// ---------------- decoupled coalesced scan (3 kernels) ----------------
__global__ void k_scan1() {                      // grid SCANB, block 1024
    __shared__ int wsum[32];
    int n = blockIdx.x * 1024 + threadIdx.x;
    int lane = threadIdx.x & 31;
    int wid = threadIdx.x >> 5;
    int v = (n < NODES) ? g_cnt[n] : 0;
    int s = v;
#pragma unroll
    for (int o = 1; o < 32; o <<= 1) {
        int t = __shfl_up_sync(0xffffffffu, s, o);
        if (lane >= o) s += t;
    }
    if (lane == 31) wsum[wid] = s;
    __syncthreads();
    if (wid == 0) {
        int t = wsum[lane];
        int u = t;
#pragma unroll
        for (int o = 1; o < 32; o <<= 1) {
            int q = __shfl_up_sync(0xffffffffu, u, o);
            if (lane >= o) u += q;
        }
        wsum[lane] = u - t;                      // exclusive over warps
    }
    __syncthreads();
    int incl = s + wsum[wid];
    if (n < NODES) g_ps[n] = incl;
    if (threadIdx.x == 1023) g_part[blockIdx.x] = incl;
}

__global__ void k_scan2() {                      // 1 block, 64 threads
    __shared__ int sm[64];
    int t = threadIdx.x;
    int v = (t < SCANB) ? g_part[t] : 0;
    sm[t] = v;
    __syncthreads();
    for (int o = 1; o < 64; o <<= 1) {
        int a = (t >= o) ? sm[t - o] : 0;
        __syncthreads();
        sm[t] += a;
        __syncthreads();
    }
    g_poff[t] = sm[t] - v;                       // exclusive
}

__global__ void k_scan3() {                      // grid SCANB, block 1024
    int n = blockIdx.x * 1024 + threadIdx.x;
    if (n < NODES) {
        int off = g_poff[blockIdx.x] + g_ps[n] - g_cnt[n];
        g_off[n] = off;
        g_cur[n] = off;
    }
    if (n == 0) g_off[NODES] = EDGES;
}

// ---------------- scatter edges into CSR buckets + precompute dist ----------------
__global__ void k_scatter(const float* __restrict__ pos) {
    int e = blockIdx.x * 256 + threadIdx.x;
    int d = g_dst[e];
    int s = g_src[e];
    float dx = __ldg(pos + 3 * s + 0) - __ldg(pos + 3 * d + 0);
    float dy = __ldg(pos + 3 * s + 1) - __ldg(pos + 3 * d + 1);
    float dz = __ldg(pos + 3 * s + 2) - __ldg(pos + 3 * d + 2);
    float dist = sqrtf(dx * dx + dy * dy + dz * dz);
    int p = atomicAdd(&g_cur[d], 1);
    ((int2*)g_sed4)[p] = make_int2(s, __float_as_int(dist));
}

// ---------------- XB[n,j] = sum_i x[n,i] * w1[4+i, j] ----------------
__global__ void k_xb(const float* __restrict__ x, const float* __restrict__ w1) {
    int i = blockIdx.x * 256 + threadIdx.x;      // NODES*HID == EDGES grid
    int n = i >> 5, j = i & 31;
    float4 xv = __ldg((const float4*)(x + ((size_t)n << 2)));
    float a = xv.x * __ldg(w1 + 4 * 32 + j);
    a = fmaf(xv.y, __ldg(w1 + 5 * 32 + j), a);
    a = fmaf(xv.z, __ldg(w1 + 6 * 32 + j), a);
    a = fmaf(xv.w, __ldg(w1 + 7 * 32 + j), a);
    g_XB[i] = a;
}

// ---------------- main: per-node gather, silu-mean, W2, softmax ----------------
__global__ void __launch_bounds__(256) k_main(const float* __restrict__ x,
                                              const float* __restrict__ w1,
                                              const float* __restrict__ b1,
                                              const float* __restrict__ w2,
                                              const float* __restrict__ b2,
                                              const float* __restrict__ pw,
                                              const float* __restrict__ pb) {
    __shared__ float sw2[HID * HID];             // [j][lane]
    __shared__ float spw[HID * KSLOT];
    __shared__ float spb[KSLOT];
    __shared__ float sh[8][HID];
    int t = threadIdx.x;
    for (int i = t; i < HID * HID; i += 256) sw2[i] = w2[i];
    for (int i = t; i < HID * KSLOT; i += 256) spw[i] = pw[i];
    if (t < KSLOT) spb[t] = pb[t];
    __syncthreads();

    int lane = t & 31;
    int w = t >> 5;

    float w1a0 = __ldg(w1 + 0 * 32 + lane);
    float w1a1 = __ldg(w1 + 1 * 32 + lane);
    float w1a2 = __ldg(w1 + 2 * 32 + lane);
    float w1a3 = __ldg(w1 + 3 * 32 + lane);
    float cw   = __ldg(w1 + 8 * 32 + lane);
    float b1r  = __ldg(b1 + lane);
    float b2r  = __ldg(b2 + lane);

    const int2* sed = (const int2*)g_sed4;

    int gw = (blockIdx.x << 3) + w;
    int nwarp = gridDim.x << 3;

    for (int node = gw; node < NODES; node += nwarp) {
        int beg = g_off[node];
        int end = g_off[node + 1];
        float4 xd = __ldg((const float4*)(x + ((size_t)node << 2)));
        float base = b1r;
        base = fmaf(xd.x, w1a0, base);
        base = fmaf(xd.y, w1a1, base);
        base = fmaf(xd.z, w1a2, base);
        base = fmaf(xd.w, w1a3, base);

        float acc0 = 0.0f, acc1 = 0.0f, acc2 = 0.0f, acc3 = 0.0f;
        int i = beg;
        if ((i & 1) && i < end) {                // align to int4 boundary
            int2 e = __ldg(sed + i);
            float xb = __ldg(g_XB + (((size_t)e.x) << 5) + lane);
            acc0 += siluf(fmaf(__int_as_float(e.y), cw, base) + xb);
            i++;
        }
        for (; i + 4 <= end; i += 4) {
            const int4* p = (const int4*)(sed + i);
            int4 a = __ldg(p);
            int4 b = __ldg(p + 1);
            float xb0 = __ldg(g_XB + (((size_t)a.x) << 5) + lane);
            float xb1 = __ldg(g_XB + (((size_t)a.z) << 5) + lane);
            float xb2 = __ldg(g_XB + (((size_t)b.x) << 5) + lane);
            float xb3 = __ldg(g_XB + (((size_t)b.z) << 5) + lane);
            acc0 += siluf(fmaf(__int_as_float(a.y), cw, base) + xb0);
            acc1 += siluf(fmaf(__int_as_float(a.w), cw, base) + xb1);
            acc2 += siluf(fmaf(__int_as_float(b.y), cw, base) + xb2);
            acc3 += siluf(fmaf(__int_as_float(b.w), cw, base) + xb3);
        }
        for (; i < end; i++) {
            int2 e = __ldg(sed + i);
            float xb = __ldg(g_XB + (((size_t)e.x) << 5) + lane);
            acc0 += siluf(fmaf(__int_as_float(e.y), cw, base) + xb);
        }

        int deg = end - beg;
        float inv = (deg > 0) ? __fdividef(1.0f, (float)deg) : 0.0f;
        float hsil = ((acc0 + acc1) + (acc2 + acc3)) * inv;

        sh[w][lane] = hsil;
        __syncwarp();
        float h = (deg > 0) ? b2r : 0.0f;
#pragma unroll
        for (int j = 0; j < 32; j++) h = fmaf(sh[w][j], sw2[j * 32 + lane], h);
        __syncwarp();

        g_H[((size_t)node << 5) + lane] = h;
        sh[w][lane] = h;
        __syncwarp();

        if (lane < 8) {
            float l = spb[lane];
#pragma unroll
            for (int j = 0; j < 32; j++) l = fmaf(sh[w][j], spw[j * 8 + lane], l);
            float m = l;
            m = fmaxf(m, __shfl_xor_sync(0xff, m, 4, 8));
            m = fmaxf(m, __shfl_xor_sync(0xff, m, 2, 8));
            m = fmaxf(m, __shfl_xor_sync(0xff, m, 1, 8));
            float ex = __expf(l - m);
            float sum = ex;
            sum += __shfl_xor_sync(0xff, sum, 4, 8);
            sum += __shfl_xor_sync(0xff, sum, 2, 8);
            sum += __shfl_xor_sync(0xff, sum, 1, 8);
            g_S[((size_t)node << 3) + lane] = __fdividef(ex, sum);
        }
        __syncwarp();
    }
}

// ---------------- pooling ----------------
__global__ void __launch_bounds__(256) k_pool() {
    int b = blockIdx.x & 15;
    int slice = blockIdx.x >> 4;

    int lo = 0, hi = NODES;
    while (lo < hi) { int m = (lo + hi) >> 1; if (g_batch[m] < b) lo = m + 1; else hi = m; }
    int start = lo;
    lo = start; hi = NODES;
    while (lo < hi) { int m = (lo + hi) >> 1; if (g_batch[m] < b + 1) lo = m + 1; else hi = m; }
    int end = lo;

    int cnt = end - start;
    int s0 = start + (cnt * slice) / 4;
    int s1 = start + (cnt * (slice + 1)) / 4;

    int k = threadIdx.x >> 5;
    int j = threadIdx.x & 31;

    float acc = 0.0f;
#pragma unroll 4
    for (int n = s0; n < s1; n++)
        acc = fmaf(__ldg(g_S + (size_t)n * KSLOT + k), __ldg(g_H + (size_t)n * HID + j), acc);

    atomicAdd(&g_POOL[(b * KSLOT + k) * HID + j], acc);
}

// ---------------- z = pooled @ toz_w + toz_b ----------------
__global__ void k_z(const float* __restrict__ tw, const float* __restrict__ tb) {
    int t = threadIdx.x;               // 512 threads
    int b = t >> 5;
    int k = (t >> 2) & 7;
    int d = t & 3;
    float acc = tb[d];
#pragma unroll
    for (int j = 0; j < HID; j++)
        acc = fmaf(g_POOL[b * 256 + k * 32 + j], tw[j * 4 + d], acc);
    g_Z[t] = acc;
}

// ---------------- decode ----------------
__global__ void __launch_bounds__(128) k_dec(const float* __restrict__ w1,
                                             const float* __restrict__ b1,
                                             const float* __restrict__ w2,
                                             const float* __restrict__ b2,
                                             float* __restrict__ out) {
    __shared__ __align__(16) float sz[NGRAPH * KSLOT * 4];
    __shared__ __align__(16) float sw1[128];
    __shared__ float sb1[32];
    __shared__ __align__(16) float sw2[128];
    __shared__ float sb2v[4];

    int t = threadIdx.x;
    for (int i = t; i < 512; i += 128) sz[i] = g_Z[i];
    sw1[t] = w1[(t & 3) * 32 + (t >> 2)];
    sw2[t] = w2[t];
    if (t < 32) sb1[t] = b1[t];
    if (t < 4)  sb2v[t] = b2[t];
    __syncthreads();

    int n = blockIdx.x * 128 + t;
    if (n >= NODES) return;

    float4 sa = *(const float4*)(g_S + (size_t)n * KSLOT);
    float4 sbv = *(const float4*)(g_S + (size_t)n * KSLOT + 4);
    float s[8] = { sa.x, sa.y, sa.z, sa.w, sbv.x, sbv.y, sbv.z, sbv.w };

#pragma unroll 1
    for (int b = 0; b < NGRAPH; b++) {
        float q0 = 0.f, q1 = 0.f, q2 = 0.f, q3 = 0.f;
#pragma unroll
        for (int k = 0; k < 8; k++) {
            float4 zv = *(const float4*)&sz[(b * 8 + k) * 4];
            q0 = fmaf(s[k], zv.x, q0);
            q1 = fmaf(s[k], zv.y, q1);
            q2 = fmaf(s[k], zv.z, q2);
            q3 = fmaf(s[k], zv.w, q3);
        }
        float o0 = sb2v[0], o1 = sb2v[1], o2 = sb2v[2], o3 = sb2v[3];
#pragma unroll
        for (int j = 0; j < 32; j++) {
            float4 wc = *(const float4*)&sw1[j * 4];
            float tt = sb1[j];
            tt = fmaf(q0, wc.x, tt);
            tt = fmaf(q1, wc.y, tt);
            tt = fmaf(q2, wc.z, tt);
            tt = fmaf(q3, wc.w, tt);
            tt = siluf(tt);
            float4 wr = *(const float4*)&sw2[j * 4];
            o0 = fmaf(tt, wr.x, o0);
            o1 = fmaf(tt, wr.y, o1);
            o2 = fmaf(tt, wr.z, o2);
            o3 = fmaf(tt, wr.w, o3);
        }
        *(float4*)(out + ((size_t)b * NODES + n) * 4) = make_float4(o0, o1, o2, o3);
    }
}

// ---------------- launch ----------------
extern "C" void kernel_launch(void* const* d_in, const int* in_sizes, int n_in,
                              void* d_out, int out_size) {
    const float* x      = (const float*)d_in[0];
    const float* pos    = (const float*)d_in[1];
    const void*  ei     = d_in[2];
    const void*  batch  = d_in[3];
    const float* enc_w1 = (const float*)d_in[4];
    const float* enc_b1 = (const float*)d_in[5];
    const float* enc_w2 = (const float*)d_in[6];
    const float* enc_b2 = (const float*)d_in[7];
    const float* pool_w = (const float*)d_in[8];
    const float* pool_b = (const float*)d_in[9];
    const float* toz_w  = (const float*)d_in[10];
    const float* toz_b  = (const float*)d_in[11];
    const float* dec_w1 = (const float*)d_in[12];
    const float* dec_b1 = (const float*)d_in[13];
    const float* dec_w2 = (const float*)d_in[14];
    const float* dec_b2 = (const float*)d_in[15];
    float* out = (float*)d_out;

    k_zero<<<(NODES + 255) / 256, 256>>>((const unsigned int*)ei);
    k_prep<<<EDGES / 256, 256>>>(ei, batch);
    k_scan1<<<SCANB, 1024>>>();
    k_scan2<<<1, 64>>>();
    k_scan3<<<SCANB, 1024>>>();
    k_scatter<<<EDGES / 256, 256>>>(pos);
    k_xb<<<EDGES / 256, 256>>>(x, enc_w1);
    k_main<<<740, 256>>>(x, enc_w1, enc_b1, enc_w2, enc_b2, pool_w, pool_b);
    k_pool<<<64, 256>>>();
    k_z<<<1, 512>>>(toz_w, toz_b);
    k_dec<<<(NODES + 127) / 128, 128>>>(dec_w1, dec_b1, dec_w2, dec_b2, out);
}

// round 5
// speedup vs baseline: 1.9600x; 1.5009x over previous
#include <cuda_runtime.h>

#define EDGES  1600000
#define NODES  50000
#define NGRAPH 16
#define KSLOT  8
#define HID    32
#define SCANB  ((NODES + 1023) / 1024)   // 49
#define AGGFLAG 0x40000000
#define AGGMASK 0x3FFFFFFF

// ---------------- static scratch (zero-initialized at module load) ----------------
__device__ int   g_src[EDGES];
__device__ int   g_dst[EDGES];
__device__ int2  g_sed[EDGES];           // CSR-sorted: {src, dist_bits}
__device__ int   g_cnt[NODES];           // zeroed at end of k_scan for next replay
__device__ int   g_agg[64];              // lookback aggregates; zeroed in k_scatxb
__device__ int   g_off[NODES + 1];
__device__ int   g_cur[NODES];
__device__ int   g_batch[NODES];
__device__ float g_XB[NODES * HID];      // x[n] @ W1[4:8]
__device__ float g_H[NODES * HID];
__device__ float g_S[NODES * KSLOT];
__device__ float g_POOL[NGRAPH * KSLOT * HID];   // zeroed in k_main block 0
__device__ float g_Z[NGRAPH * KSLOT * 4];

// silu(a) = a*sigmoid(a) = h + h*tanh(h), h = a/2  (single MUFU.TANH)
__device__ __forceinline__ float siluf(float a) {
    float h = a * 0.5f;
    float t;
    asm("tanh.approx.f32 %0, %1;" : "=f"(t) : "f"(h));
    return fmaf(h, t, h);
}

// ---------------- 1: convert indices + dst histogram + batch (+dtype detect) ----------------
__global__ void k_prep(const void* __restrict__ ei, const void* __restrict__ batch) {
    __shared__ int s64;
    if (threadIdx.x == 0) {
        int is64 = 1;
        const unsigned int* e = (const unsigned int*)ei;
        for (int k = 1; k < 64; k += 2)
            if (e[k] != 0u) { is64 = 0; break; }
        s64 = is64;
    }
    __syncthreads();
    int is64 = s64;
    int i = blockIdx.x * 256 + threadIdx.x;      // grid covers EDGES exactly
    int s, d;
    if (is64) {
        const long long* q = (const long long*)ei;
        s = (int)q[i];
        d = (int)q[EDGES + i];
    } else {
        const int* q = (const int*)ei;
        s = q[i];
        d = q[EDGES + i];
    }
    g_src[i] = s;
    g_dst[i] = d;
    atomicAdd(&g_cnt[d], 1);
    if (i < NODES) {
        g_batch[i] = is64 ? (int)((const long long*)batch)[i]
                          : ((const int*)batch)[i];
    }
}

// ---------------- 2: single-kernel decoupled-lookback scan ----------------
__global__ void __launch_bounds__(1024) k_scan() {   // grid SCANB, 1024 thr
    __shared__ int wsum[32];
    __shared__ int sbase;
    int b = blockIdx.x;
    int n = b * 1024 + threadIdx.x;
    int lane = threadIdx.x & 31;
    int wid = threadIdx.x >> 5;
    int v = (n < NODES) ? g_cnt[n] : 0;
    int s = v;
#pragma unroll
    for (int o = 1; o < 32; o <<= 1) {
        int t = __shfl_up_sync(0xffffffffu, s, o);
        if (lane >= o) s += t;
    }
    if (lane == 31) wsum[wid] = s;
    __syncthreads();
    if (wid == 0) {
        int t = wsum[lane];
        int u = t;
#pragma unroll
        for (int o = 1; o < 32; o <<= 1) {
            int q = __shfl_up_sync(0xffffffffu, u, o);
            if (lane >= o) u += q;
        }
        wsum[lane] = u - t;                      // exclusive over warps
    }
    __syncthreads();
    int incl = s + wsum[wid];
    if (threadIdx.x == 1023)                     // publish block aggregate
        atomicExch(&g_agg[b], incl | AGGFLAG);
    if (wid == 0) {                              // parallel lookback over predecessors
        int sum = 0;
        for (int p = lane; p < b; p += 32) {
            int a;
            do { a = atomicAdd(&g_agg[p], 0); } while (!(a & AGGFLAG));
            sum += a & AGGMASK;
        }
#pragma unroll
        for (int o = 16; o; o >>= 1) sum += __shfl_xor_sync(0xffffffffu, sum, o);
        if (lane == 0) sbase = sum;
    }
    __syncthreads();
    if (n < NODES) {
        int off = sbase + incl - v;              // global exclusive prefix
        g_off[n] = off;
        g_cur[n] = off;
        g_cnt[n] = 0;                            // reset for next graph replay
    }
    if (n == 0) g_off[NODES] = EDGES;
}

// ---------------- 3: fused scatter (CSR bucket + dist) and XB precompute ----------------
__global__ void k_scatxb(const float* __restrict__ pos, const float* __restrict__ x,
                         const float* __restrict__ w1) {
    int i = blockIdx.x * 256 + threadIdx.x;      // EDGES == NODES*HID
    int d = g_dst[i];
    int s = g_src[i];
    float dx = __ldg(pos + 3 * s + 0) - __ldg(pos + 3 * d + 0);
    float dy = __ldg(pos + 3 * s + 1) - __ldg(pos + 3 * d + 1);
    float dz = __ldg(pos + 3 * s + 2) - __ldg(pos + 3 * d + 2);
    float dist = sqrtf(dx * dx + dy * dy + dz * dz);
    int p = atomicAdd(&g_cur[d], 1);
    g_sed[p] = make_int2(s, __float_as_int(dist));

    {   // XB[n,j] = sum_i x[n,i]*w1[4+i,j]
        int n = i >> 5, j = i & 31;
        float4 xv = __ldg((const float4*)(x + ((size_t)n << 2)));
        float a = xv.x * __ldg(w1 + 4 * 32 + j);
        a = fmaf(xv.y, __ldg(w1 + 5 * 32 + j), a);
        a = fmaf(xv.z, __ldg(w1 + 6 * 32 + j), a);
        a = fmaf(xv.w, __ldg(w1 + 7 * 32 + j), a);
        g_XB[i] = a;
    }
    if (i < 64) g_agg[i] = 0;                    // reset lookback flags for next replay
}

// ---------------- 4: main gather + silu-mean + W2 + softmax ----------------
__global__ void __launch_bounds__(256) k_main(const float* __restrict__ x,
                                              const float* __restrict__ w1,
                                              const float* __restrict__ b1,
                                              const float* __restrict__ w2,
                                              const float* __restrict__ b2,
                                              const float* __restrict__ pw,
                                              const float* __restrict__ pb) {
    __shared__ float sw2[HID * HID];
    __shared__ float spw[HID * KSLOT];
    __shared__ float spb[KSLOT];
    __shared__ float sh[8][HID];
    int t = threadIdx.x;
    if (blockIdx.x == 0)                         // zero pool accumulator for k_pool
        for (int i = t; i < NGRAPH * KSLOT * HID; i += 256) g_POOL[i] = 0.0f;
    for (int i = t; i < HID * HID; i += 256) sw2[i] = w2[i];
    for (int i = t; i < HID * KSLOT; i += 256) spw[i] = pw[i];
    if (t < KSLOT) spb[t] = pb[t];
    __syncthreads();

    int lane = t & 31;
    int w = t >> 5;

    float w1a0 = __ldg(w1 + 0 * 32 + lane);
    float w1a1 = __ldg(w1 + 1 * 32 + lane);
    float w1a2 = __ldg(w1 + 2 * 32 + lane);
    float w1a3 = __ldg(w1 + 3 * 32 + lane);
    float cw   = __ldg(w1 + 8 * 32 + lane);
    float b1r  = __ldg(b1 + lane);
    float b2r  = __ldg(b2 + lane);

    const int2* sed = (const int2*)g_sed;

    int gw = (blockIdx.x << 3) + w;
    int nwarp = gridDim.x << 3;

    for (int node = gw; node < NODES; node += nwarp) {
        int beg = g_off[node];
        int end = g_off[node + 1];
        float4 xd = __ldg((const float4*)(x + ((size_t)node << 2)));
        float base = b1r;
        base = fmaf(xd.x, w1a0, base);
        base = fmaf(xd.y, w1a1, base);
        base = fmaf(xd.z, w1a2, base);
        base = fmaf(xd.w, w1a3, base);

        float acc0 = 0.0f, acc1 = 0.0f, acc2 = 0.0f, acc3 = 0.0f;
        int i = beg;
        for (; i + 8 <= end; i += 8) {
            int2 e[8];
            float xb[8];
#pragma unroll
            for (int k = 0; k < 8; k++) e[k] = __ldg(sed + i + k);
#pragma unroll
            for (int k = 0; k < 8; k++)
                xb[k] = __ldg(g_XB + (((size_t)e[k].x) << 5) + lane);
#pragma unroll
            for (int k = 0; k < 8; k++) {
                float pre = fmaf(__int_as_float(e[k].y), cw, base) + xb[k];
                float sv = siluf(pre);
                if ((k & 3) == 0) acc0 += sv;
                else if ((k & 3) == 1) acc1 += sv;
                else if ((k & 3) == 2) acc2 += sv;
                else acc3 += sv;
            }
        }
        for (; i < end; i++) {
            int2 e = __ldg(sed + i);
            float xb = __ldg(g_XB + (((size_t)e.x) << 5) + lane);
            acc0 += siluf(fmaf(__int_as_float(e.y), cw, base) + xb);
        }

        int deg = end - beg;
        float inv = (deg > 0) ? __fdividef(1.0f, (float)deg) : 0.0f;
        float hsil = ((acc0 + acc1) + (acc2 + acc3)) * inv;

        sh[w][lane] = hsil;
        __syncwarp();
        float h = (deg > 0) ? b2r : 0.0f;
#pragma unroll
        for (int j = 0; j < 32; j++) h = fmaf(sh[w][j], sw2[j * 32 + lane], h);
        __syncwarp();

        g_H[((size_t)node << 5) + lane] = h;
        sh[w][lane] = h;
        __syncwarp();

        if (lane < 8) {
            float l = spb[lane];
#pragma unroll
            for (int j = 0; j < 32; j++) l = fmaf(sh[w][j], spw[j * 8 + lane], l);
            float m = l;
            m = fmaxf(m, __shfl_xor_sync(0xff, m, 4, 8));
            m = fmaxf(m, __shfl_xor_sync(0xff, m, 2, 8));
            m = fmaxf(m, __shfl_xor_sync(0xff, m, 1, 8));
            float ex = __expf(l - m);
            float sum = ex;
            sum += __shfl_xor_sync(0xff, sum, 4, 8);
            sum += __shfl_xor_sync(0xff, sum, 2, 8);
            sum += __shfl_xor_sync(0xff, sum, 1, 8);
            g_S[((size_t)node << 3) + lane] = __fdividef(ex, sum);
        }
        __syncwarp();
    }
}

// ---------------- 5: pooling (16 graphs x 16 slices = 256 blocks) ----------------
__global__ void __launch_bounds__(256) k_pool() {
    int b = blockIdx.x & 15;
    int slice = blockIdx.x >> 4;

    int lo = 0, hi = NODES;
    while (lo < hi) { int m = (lo + hi) >> 1; if (g_batch[m] < b) lo = m + 1; else hi = m; }
    int start = lo;
    lo = start; hi = NODES;
    while (lo < hi) { int m = (lo + hi) >> 1; if (g_batch[m] < b + 1) lo = m + 1; else hi = m; }
    int end = lo;

    int cnt = end - start;
    int s0 = start + (cnt * slice) / 16;
    int s1 = start + (cnt * (slice + 1)) / 16;

    int k = threadIdx.x >> 5;
    int j = threadIdx.x & 31;

    float acc = 0.0f;
#pragma unroll 8
    for (int n = s0; n < s1; n++)
        acc = fmaf(__ldg(g_S + (size_t)n * KSLOT + k), __ldg(g_H + (size_t)n * HID + j), acc);

    atomicAdd(&g_POOL[(b * KSLOT + k) * HID + j], acc);
}

// ---------------- 6: z = pooled @ toz_w + toz_b ----------------
__global__ void k_z(const float* __restrict__ tw, const float* __restrict__ tb) {
    int t = threadIdx.x;               // 512 threads
    int b = t >> 5;
    int k = (t >> 2) & 7;
    int d = t & 3;
    float acc = tb[d];
#pragma unroll
    for (int j = 0; j < HID; j++)
        acc = fmaf(g_POOL[b * 256 + k * 32 + j], tw[j * 4 + d], acc);
    g_Z[t] = acc;
}

// ---------------- 7: decode ----------------
__global__ void __launch_bounds__(128) k_dec(const float* __restrict__ w1,
                                             const float* __restrict__ b1,
                                             const float* __restrict__ w2,
                                             const float* __restrict__ b2,
                                             float* __restrict__ out) {
    __shared__ __align__(16) float sz[NGRAPH * KSLOT * 4];
    __shared__ __align__(16) float sw1[128];
    __shared__ float sb1[32];
    __shared__ __align__(16) float sw2[128];
    __shared__ float sb2v[4];

    int t = threadIdx.x;
    for (int i = t; i < 512; i += 128) sz[i] = g_Z[i];
    sw1[t] = w1[(t & 3) * 32 + (t >> 2)];
    sw2[t] = w2[t];
    if (t < 32) sb1[t] = b1[t];
    if (t < 4)  sb2v[t] = b2[t];
    __syncthreads();

    int n = blockIdx.x * 128 + t;
    if (n >= NODES) return;

    float4 sa = *(const float4*)(g_S + (size_t)n * KSLOT);
    float4 sbv = *(const float4*)(g_S + (size_t)n * KSLOT + 4);
    float s[8] = { sa.x, sa.y, sa.z, sa.w, sbv.x, sbv.y, sbv.z, sbv.w };

#pragma unroll 1
    for (int b = 0; b < NGRAPH; b++) {
        float q0 = 0.f, q1 = 0.f, q2 = 0.f, q3 = 0.f;
#pragma unroll
        for (int k = 0; k < 8; k++) {
            float4 zv = *(const float4*)&sz[(b * 8 + k) * 4];
            q0 = fmaf(s[k], zv.x, q0);
            q1 = fmaf(s[k], zv.y, q1);
            q2 = fmaf(s[k], zv.z, q2);
            q3 = fmaf(s[k], zv.w, q3);
        }
        float o0 = sb2v[0], o1 = sb2v[1], o2 = sb2v[2], o3 = sb2v[3];
#pragma unroll
        for (int j = 0; j < 32; j++) {
            float4 wc = *(const float4*)&sw1[j * 4];
            float tt = sb1[j];
            tt = fmaf(q0, wc.x, tt);
            tt = fmaf(q1, wc.y, tt);
            tt = fmaf(q2, wc.z, tt);
            tt = fmaf(q3, wc.w, tt);
            tt = siluf(tt);
            float4 wr = *(const float4*)&sw2[j * 4];
            o0 = fmaf(tt, wr.x, o0);
            o1 = fmaf(tt, wr.y, o1);
            o2 = fmaf(tt, wr.z, o2);
            o3 = fmaf(tt, wr.w, o3);
        }
        *(float4*)(out + ((size_t)b * NODES + n) * 4) = make_float4(o0, o1, o2, o3);
    }
}

// ---------------- launch ----------------
extern "C" void kernel_launch(void* const* d_in, const int* in_sizes, int n_in,
                              void* d_out, int out_size) {
    const float* x      = (const float*)d_in[0];
    const float* pos    = (const float*)d_in[1];
    const void*  ei     = d_in[2];
    const void*  batch  = d_in[3];
    const float* enc_w1 = (const float*)d_in[4];
    const float* enc_b1 = (const float*)d_in[5];
    const float* enc_w2 = (const float*)d_in[6];
    const float* enc_b2 = (const float*)d_in[7];
    const float* pool_w = (const float*)d_in[8];
    const float* pool_b = (const float*)d_in[9];
    const float* toz_w  = (const float*)d_in[10];
    const float* toz_b  = (const float*)d_in[11];
    const float* dec_w1 = (const float*)d_in[12];
    const float* dec_b1 = (const float*)d_in[13];
    const float* dec_w2 = (const float*)d_in[14];
    const float* dec_b2 = (const float*)d_in[15];
    float* out = (float*)d_out;

    k_prep<<<EDGES / 256, 256>>>(ei, batch);                 // 1
    k_scan<<<SCANB, 1024>>>();                               // 2
    k_scatxb<<<EDGES / 256, 256>>>(pos, x, enc_w1);          // 3
    k_main<<<740, 256>>>(x, enc_w1, enc_b1, enc_w2, enc_b2,  // 4  <- profiled slot
                         pool_w, pool_b);
    k_pool<<<256, 256>>>();                                  // 5
    k_z<<<1, 512>>>(toz_w, toz_b);                           // 6
    k_dec<<<(NODES + 127) / 128, 128>>>(dec_w1, dec_b1, dec_w2, dec_b2, out);  // 7
}

// round 6
// speedup vs baseline: 2.1039x; 1.0734x over previous
#include <cuda_runtime.h>

#define EDGES  1600000
#define NODES  50000
#define NGRAPH 16
#define KSLOT  8
#define HID    32
#define SCANB  ((NODES + 1023) / 1024)   // 49
#define AGGFLAG 0x40000000
#define AGGMASK 0x3FFFFFFF

// ---------------- static scratch (zero-initialized at module load) ----------------
__device__ int   g_src[EDGES];
__device__ int   g_dst[EDGES];
__device__ int2  g_sed[EDGES];           // CSR-sorted: {src, dist_bits}
__device__ int   g_cnt[NODES];           // re-zeroed in k_scan
__device__ int   g_agg[64];              // lookback aggregates; re-zeroed in k_scatxb
__device__ int   g_off[NODES + 1];
__device__ int   g_cur[NODES];
__device__ int   g_batch[NODES];
__device__ float g_XB[NODES * HID];      // 0.5 * (x[n] @ W1[4:8])
__device__ float g_H[NODES * HID];
__device__ float g_S[NODES * KSLOT];
__device__ float g_POOL[NGRAPH * KSLOT * HID];   // zeroed in k_main block 0
__device__ float g_Z[NGRAPH * KSLOT * 4];
__device__ unsigned g_poolcnt;           // re-zeroed by last pool block

// silu(a) = a*sigmoid(a) = h + h*tanh(h), h = a/2  (single MUFU.TANH)
// callers pass h directly (inputs pre-halved)
__device__ __forceinline__ float silu_h(float h) {
    float t;
    asm("tanh.approx.f32 %0, %1;" : "=f"(t) : "f"(h));
    return fmaf(h, t, h);
}
__device__ __forceinline__ float siluf(float a) { return silu_h(a * 0.5f); }

// ---------------- 1: convert indices + dst histogram + batch ----------------
// grid 3125, block 128; 4 edges per thread
__global__ void k_prep(const void* __restrict__ ei, const void* __restrict__ batch) {
    __shared__ int s64;
    if (threadIdx.x == 0) {
        int is64 = 1;
        const unsigned int* e = (const unsigned int*)ei;
        for (int k = 1; k < 64; k += 2)
            if (e[k] != 0u) { is64 = 0; break; }
        s64 = is64;
    }
    __syncthreads();
    int is64 = s64;
    int tid = blockIdx.x * 128 + threadIdx.x;
    int base = tid * 4;
    int4 sv, dv;
    if (is64) {
        const longlong2* q = (const longlong2*)ei;
        longlong2 a = __ldg(q + (base >> 1));
        longlong2 b = __ldg(q + (base >> 1) + 1);
        sv = make_int4((int)a.x, (int)a.y, (int)b.x, (int)b.y);
        longlong2 c = __ldg(q + ((EDGES + base) >> 1));
        longlong2 d = __ldg(q + ((EDGES + base) >> 1) + 1);
        dv = make_int4((int)c.x, (int)c.y, (int)d.x, (int)d.y);
    } else {
        sv = __ldg((const int4*)((const int*)ei + base));
        dv = __ldg((const int4*)((const int*)ei + EDGES + base));
    }
    *(int4*)(g_src + base) = sv;
    *(int4*)(g_dst + base) = dv;
    atomicAdd(&g_cnt[dv.x], 1);
    atomicAdd(&g_cnt[dv.y], 1);
    atomicAdd(&g_cnt[dv.z], 1);
    atomicAdd(&g_cnt[dv.w], 1);
    if (base < NODES) {                          // NODES % 4 == 0
        int4 bv;
        if (is64) {
            const longlong2* q = (const longlong2*)batch;
            longlong2 a = __ldg(q + (base >> 1));
            longlong2 b = __ldg(q + (base >> 1) + 1);
            bv = make_int4((int)a.x, (int)a.y, (int)b.x, (int)b.y);
        } else {
            bv = __ldg((const int4*)((const int*)batch + base));
        }
        *(int4*)(g_batch + base) = bv;
    }
}

// ---------------- 2: single-kernel decoupled-lookback scan ----------------
__global__ void __launch_bounds__(1024) k_scan() {   // grid SCANB
    __shared__ int wsum[32];
    __shared__ int sbase;
    int b = blockIdx.x;
    int n = b * 1024 + threadIdx.x;
    int lane = threadIdx.x & 31;
    int wid = threadIdx.x >> 5;
    int v = (n < NODES) ? g_cnt[n] : 0;
    int s = v;
#pragma unroll
    for (int o = 1; o < 32; o <<= 1) {
        int t = __shfl_up_sync(0xffffffffu, s, o);
        if (lane >= o) s += t;
    }
    if (lane == 31) wsum[wid] = s;
    __syncthreads();
    if (wid == 0) {
        int t = wsum[lane];
        int u = t;
#pragma unroll
        for (int o = 1; o < 32; o <<= 1) {
            int q = __shfl_up_sync(0xffffffffu, u, o);
            if (lane >= o) u += q;
        }
        wsum[lane] = u - t;
    }
    __syncthreads();
    int incl = s + wsum[wid];
    if (threadIdx.x == 1023)
        atomicExch(&g_agg[b], incl | AGGFLAG);
    if (wid == 0) {
        int sum = 0;
        for (int p = lane; p < b; p += 32) {
            int a;
            do { a = atomicAdd(&g_agg[p], 0); } while (!(a & AGGFLAG));
            sum += a & AGGMASK;
        }
#pragma unroll
        for (int o = 16; o; o >>= 1) sum += __shfl_xor_sync(0xffffffffu, sum, o);
        if (lane == 0) sbase = sum;
    }
    __syncthreads();
    if (n < NODES) {
        int off = sbase + incl - v;
        g_off[n] = off;
        g_cur[n] = off;
        g_cnt[n] = 0;                            // reset for next replay
    }
    if (n == 0) g_off[NODES] = EDGES;
}

// ---------------- 3: fused scatter + XB precompute (2 edges/thread) ----------------
// grid 3125, block 256
__global__ void __launch_bounds__(256) k_scatxb(const float* __restrict__ pos,
                                                const float* __restrict__ x,
                                                const float* __restrict__ w1) {
    int tid = blockIdx.x * 256 + threadIdx.x;
    int i0 = tid * 2;
    int2 dp = *(const int2*)(g_dst + i0);
    int2 sp = *(const int2*)(g_src + i0);

    float s0x = __ldg(pos + 3 * sp.x), s0y = __ldg(pos + 3 * sp.x + 1), s0z = __ldg(pos + 3 * sp.x + 2);
    float d0x = __ldg(pos + 3 * dp.x), d0y = __ldg(pos + 3 * dp.x + 1), d0z = __ldg(pos + 3 * dp.x + 2);
    float s1x = __ldg(pos + 3 * sp.y), s1y = __ldg(pos + 3 * sp.y + 1), s1z = __ldg(pos + 3 * sp.y + 2);
    float d1x = __ldg(pos + 3 * dp.y), d1y = __ldg(pos + 3 * dp.y + 1), d1z = __ldg(pos + 3 * dp.y + 2);
    float ax = s0x - d0x, ay = s0y - d0y, az = s0z - d0z;
    float bx = s1x - d1x, by = s1y - d1y, bz = s1z - d1z;
    float dist0 = sqrtf(fmaf(ax, ax, fmaf(ay, ay, az * az)));
    float dist1 = sqrtf(fmaf(bx, bx, fmaf(by, by, bz * bz)));
    int p0 = atomicAdd(&g_cur[dp.x], 1);
    int p1 = atomicAdd(&g_cur[dp.y], 1);
    g_sed[p0] = make_int2(sp.x, __float_as_int(dist0));
    g_sed[p1] = make_int2(sp.y, __float_as_int(dist1));

    {   // XB for flat indices i0, i0+1 (same node row; adjacent columns)
        int n = i0 >> 5, j = i0 & 31;
        float4 xv = __ldg((const float4*)(x + ((size_t)n << 2)));
        float a0 = xv.x * __ldg(w1 + 4 * 32 + j);
        float a1 = xv.x * __ldg(w1 + 4 * 32 + j + 1);
        a0 = fmaf(xv.y, __ldg(w1 + 5 * 32 + j),     a0);
        a1 = fmaf(xv.y, __ldg(w1 + 5 * 32 + j + 1), a1);
        a0 = fmaf(xv.z, __ldg(w1 + 6 * 32 + j),     a0);
        a1 = fmaf(xv.z, __ldg(w1 + 6 * 32 + j + 1), a1);
        a0 = fmaf(xv.w, __ldg(w1 + 7 * 32 + j),     a0);
        a1 = fmaf(xv.w, __ldg(w1 + 7 * 32 + j + 1), a1);
        *(float2*)(g_XB + i0) = make_float2(a0 * 0.5f, a1 * 0.5f);   // pre-halved
    }
    if (tid < 64) g_agg[tid] = 0;                // reset lookback flags
}

// ---------------- 4: main gather + silu-mean + W2 + softmax ----------------
__global__ void __launch_bounds__(256, 8) k_main(const float* __restrict__ x,
                                                 const float* __restrict__ w1,
                                                 const float* __restrict__ b1,
                                                 const float* __restrict__ w2,
                                                 const float* __restrict__ b2,
                                                 const float* __restrict__ pw,
                                                 const float* __restrict__ pb) {
    __shared__ float sw2[HID * HID];
    __shared__ float spw[HID * KSLOT];
    __shared__ float spb[KSLOT];
    __shared__ float sh[8][HID];
    int t = threadIdx.x;
    if (blockIdx.x == 0)
        for (int i = t; i < NGRAPH * KSLOT * HID; i += 256) g_POOL[i] = 0.0f;
    for (int i = t; i < HID * HID; i += 256) sw2[i] = w2[i];
    for (int i = t; i < HID * KSLOT; i += 256) spw[i] = pw[i];
    if (t < KSLOT) spb[t] = pb[t];
    __syncthreads();

    int lane = t & 31;
    int w = t >> 5;

    // pre-halved layer-1 params: h = 0.5*pre arrives straight from the FMA chain
    float w1a0 = 0.5f * __ldg(w1 + 0 * 32 + lane);
    float w1a1 = 0.5f * __ldg(w1 + 1 * 32 + lane);
    float w1a2 = 0.5f * __ldg(w1 + 2 * 32 + lane);
    float w1a3 = 0.5f * __ldg(w1 + 3 * 32 + lane);
    float cw   = 0.5f * __ldg(w1 + 8 * 32 + lane);
    float b1r  = 0.5f * __ldg(b1 + lane);
    float b2r  = __ldg(b2 + lane);

    const int2* sed = (const int2*)g_sed;

    int gw = (blockIdx.x << 3) + w;
    int nwarp = gridDim.x << 3;

    for (int node = gw; node < NODES; node += nwarp) {
        int beg = g_off[node];
        int end = g_off[node + 1];
        float4 xd = __ldg((const float4*)(x + ((size_t)node << 2)));
        float base = b1r;
        base = fmaf(xd.x, w1a0, base);
        base = fmaf(xd.y, w1a1, base);
        base = fmaf(xd.z, w1a2, base);
        base = fmaf(xd.w, w1a3, base);

        float acc0 = 0.0f, acc1 = 0.0f, acc2 = 0.0f, acc3 = 0.0f;
        int i = beg;
        for (; i + 8 <= end; i += 8) {
            int2 e[8];
            float xb[8];
#pragma unroll
            for (int k = 0; k < 8; k++) e[k] = __ldg(sed + i + k);
#pragma unroll
            for (int k = 0; k < 8; k++)
                xb[k] = __ldg(g_XB + (((size_t)e[k].x) << 5) + lane);
#pragma unroll
            for (int k = 0; k < 8; k++) {
                float h = fmaf(__int_as_float(e[k].y), cw, base) + xb[k];
                float sv = silu_h(h);
                if ((k & 3) == 0) acc0 += sv;
                else if ((k & 3) == 1) acc1 += sv;
                else if ((k & 3) == 2) acc2 += sv;
                else acc3 += sv;
            }
        }
        for (; i < end; i++) {
            int2 e = __ldg(sed + i);
            float xb = __ldg(g_XB + (((size_t)e.x) << 5) + lane);
            acc0 += silu_h(fmaf(__int_as_float(e.y), cw, base) + xb);
        }

        int deg = end - beg;
        float inv = (deg > 0) ? __fdividef(1.0f, (float)deg) : 0.0f;
        float hsil = ((acc0 + acc1) + (acc2 + acc3)) * inv;

        sh[w][lane] = hsil;
        __syncwarp();
        float h = (deg > 0) ? b2r : 0.0f;
#pragma unroll
        for (int j = 0; j < 32; j++) h = fmaf(sh[w][j], sw2[j * 32 + lane], h);
        __syncwarp();

        g_H[((size_t)node << 5) + lane] = h;
        sh[w][lane] = h;
        __syncwarp();

        if (lane < 8) {
            float l = spb[lane];
#pragma unroll
            for (int j = 0; j < 32; j++) l = fmaf(sh[w][j], spw[j * 8 + lane], l);
            float m = l;
            m = fmaxf(m, __shfl_xor_sync(0xff, m, 4, 8));
            m = fmaxf(m, __shfl_xor_sync(0xff, m, 2, 8));
            m = fmaxf(m, __shfl_xor_sync(0xff, m, 1, 8));
            float ex = __expf(l - m);
            float sum = ex;
            sum += __shfl_xor_sync(0xff, sum, 4, 8);
            sum += __shfl_xor_sync(0xff, sum, 2, 8);
            sum += __shfl_xor_sync(0xff, sum, 1, 8);
            g_S[((size_t)node << 3) + lane] = __fdividef(ex, sum);
        }
        __syncwarp();
    }
}

// ---------------- 5: pooling (256 blocks) + fused z in last block ----------------
__global__ void __launch_bounds__(256) k_pool(const float* __restrict__ tw,
                                              const float* __restrict__ tb) {
    int b = blockIdx.x & 15;
    int slice = blockIdx.x >> 4;

    int lo = 0, hi = NODES;
    while (lo < hi) { int m = (lo + hi) >> 1; if (g_batch[m] < b) lo = m + 1; else hi = m; }
    int start = lo;
    lo = start; hi = NODES;
    while (lo < hi) { int m = (lo + hi) >> 1; if (g_batch[m] < b + 1) lo = m + 1; else hi = m; }
    int end = lo;

    int cnt = end - start;
    int s0 = start + (cnt * slice) / 16;
    int s1 = start + (cnt * (slice + 1)) / 16;

    int k = threadIdx.x >> 5;
    int j = threadIdx.x & 31;

    float acc = 0.0f;
#pragma unroll 8
    for (int n = s0; n < s1; n++)
        acc = fmaf(__ldg(g_S + (size_t)n * KSLOT + k), __ldg(g_H + (size_t)n * HID + j), acc);

    atomicAdd(&g_POOL[(b * KSLOT + k) * HID + j], acc);
    __threadfence();

    __shared__ unsigned slast;
    if (threadIdx.x == 0) slast = atomicAdd(&g_poolcnt, 1u);
    __syncthreads();
    if (slast == 255) {                          // last block computes z
        for (int it = threadIdx.x; it < NGRAPH * KSLOT * 4; it += 256) {
            int bb = it >> 5;
            int kk = (it >> 2) & 7;
            int dd = it & 3;
            float acc2 = __ldg(tb + dd);
#pragma unroll
            for (int jj = 0; jj < HID; jj++)
                acc2 = fmaf(__ldcg(&g_POOL[bb * 256 + kk * 32 + jj]),
                            __ldg(tw + jj * 4 + dd), acc2);
            g_Z[it] = acc2;
        }
        if (threadIdx.x == 0) g_poolcnt = 0;     // reset for next replay
    }
}

// ---------------- 6: decode ----------------
__global__ void __launch_bounds__(128) k_dec(const float* __restrict__ w1,
                                             const float* __restrict__ b1,
                                             const float* __restrict__ w2,
                                             const float* __restrict__ b2,
                                             float* __restrict__ out) {
    __shared__ __align__(16) float sz[NGRAPH * KSLOT * 4];
    __shared__ __align__(16) float sw1[128];
    __shared__ float sb1[32];
    __shared__ __align__(16) float sw2[128];
    __shared__ float sb2v[4];

    int t = threadIdx.x;
    for (int i = t; i < 512; i += 128) sz[i] = g_Z[i];
    sw1[t] = w1[(t & 3) * 32 + (t >> 2)];
    sw2[t] = w2[t];
    if (t < 32) sb1[t] = b1[t];
    if (t < 4)  sb2v[t] = b2[t];
    __syncthreads();

    int n = blockIdx.x * 128 + t;
    if (n >= NODES) return;

    float4 sa = *(const float4*)(g_S + (size_t)n * KSLOT);
    float4 sbv = *(const float4*)(g_S + (size_t)n * KSLOT + 4);
    float s[8] = { sa.x, sa.y, sa.z, sa.w, sbv.x, sbv.y, sbv.z, sbv.w };

#pragma unroll 1
    for (int b = 0; b < NGRAPH; b++) {
        float q0 = 0.f, q1 = 0.f, q2 = 0.f, q3 = 0.f;
#pragma unroll
        for (int k = 0; k < 8; k++) {
            float4 zv = *(const float4*)&sz[(b * 8 + k) * 4];
            q0 = fmaf(s[k], zv.x, q0);
            q1 = fmaf(s[k], zv.y, q1);
            q2 = fmaf(s[k], zv.z, q2);
            q3 = fmaf(s[k], zv.w, q3);
        }
        float o0 = sb2v[0], o1 = sb2v[1], o2 = sb2v[2], o3 = sb2v[3];
#pragma unroll
        for (int j = 0; j < 32; j++) {
            float4 wc = *(const float4*)&sw1[j * 4];
            float tt = sb1[j];
            tt = fmaf(q0, wc.x, tt);
            tt = fmaf(q1, wc.y, tt);
            tt = fmaf(q2, wc.z, tt);
            tt = fmaf(q3, wc.w, tt);
            tt = siluf(tt);
            float4 wr = *(const float4*)&sw2[j * 4];
            o0 = fmaf(tt, wr.x, o0);
            o1 = fmaf(tt, wr.y, o1);
            o2 = fmaf(tt, wr.z, o2);
            o3 = fmaf(tt, wr.w, o3);
        }
        *(float4*)(out + ((size_t)b * NODES + n) * 4) = make_float4(o0, o1, o2, o3);
    }
}

// ---------------- launch ----------------
extern "C" void kernel_launch(void* const* d_in, const int* in_sizes, int n_in,
                              void* d_out, int out_size) {
    const float* x      = (const float*)d_in[0];
    const float* pos    = (const float*)d_in[1];
    const void*  ei     = d_in[2];
    const void*  batch  = d_in[3];
    const float* enc_w1 = (const float*)d_in[4];
    const float* enc_b1 = (const float*)d_in[5];
    const float* enc_w2 = (const float*)d_in[6];
    const float* enc_b2 = (const float*)d_in[7];
    const float* pool_w = (const float*)d_in[8];
    const float* pool_b = (const float*)d_in[9];
    const float* toz_w  = (const float*)d_in[10];
    const float* toz_b  = (const float*)d_in[11];
    const float* dec_w1 = (const float*)d_in[12];
    const float* dec_b1 = (const float*)d_in[13];
    const float* dec_w2 = (const float*)d_in[14];
    const float* dec_b2 = (const float*)d_in[15];
    float* out = (float*)d_out;

    k_prep<<<3125, 128>>>(ei, batch);                        // 1 (4 edges/thread)
    k_scan<<<SCANB, 1024>>>();                               // 2
    k_scatxb<<<3125, 256>>>(pos, x, enc_w1);                 // 3 (2 edges/thread)
    k_main<<<1184, 256>>>(x, enc_w1, enc_b1, enc_w2, enc_b2, // 4  <- profiled slot
                          pool_w, pool_b);
    k_pool<<<256, 256>>>(toz_w, toz_b);                      // 5 (+fused z)
    k_dec<<<(NODES + 127) / 128, 128>>>(dec_w1, dec_b1, dec_w2, dec_b2, out);  // 6
}